// round 2
// baseline (speedup 1.0000x reference)
#include <cuda_runtime.h>

#define BDIM   128
#define CH     32
#define OB     64
#define BBLK   32
#define KSPLIT 16
#define BATCH  256
#define HID    512
#define DIN    2048

#define N0 (HID * DIN)   // layer-0 params
#define N1 (HID * HID)   // layer-1/2 params
#define R_OFF1 (N0)
#define R_OFF2 (N0 + N1)
#define NTOT   (N0 + 2 * N1)

typedef unsigned long long ull;

// ---- device scratch (no allocations allowed) ----
__device__ float g_r[NTOT];                    // 1/(scale+eps), all 3 layers
__device__ float g_c[NTOT];                    // -t * r, all 3 layers
__device__ float g_part[KSPLIT * BATCH * HID]; // split-K partials
__device__ float g_f1[BATCH * HID];
__device__ float g_f2[BATCH * HID];

// ---- packed f32x2 helpers ----
__device__ __forceinline__ void fma2(ull& d, ull a, ull b, ull c) {
    asm("fma.rn.f32x2 %0, %1, %2, %3;" : "=l"(d) : "l"(a), "l"(b), "l"(c));
}
__device__ __forceinline__ void mul2(ull& d, ull a, ull b) {
    asm("mul.rn.f32x2 %0, %1, %2;" : "=l"(d) : "l"(a), "l"(b));
}
__device__ __forceinline__ ull pack2(float lo, float hi) {
    ull r; asm("mov.b64 %0, {%1, %2};" : "=l"(r) : "f"(lo), "f"(hi)); return r;
}
__device__ __forceinline__ void unpack2(float& lo, float& hi, ull v) {
    asm("mov.b64 {%0, %1}, %2;" : "=f"(lo), "=f"(hi) : "l"(v));
}
__device__ __forceinline__ float ex2f(float g) {
    float e; asm("ex2.approx.ftz.f32 %0, %1;" : "=f"(e) : "f"(g)); return e;
}

// ---- merged param transform for all 3 layers ----
__global__ void prep_all_kernel(const float* __restrict__ t0, const float* __restrict__ s0,
                                const float* __restrict__ t1, const float* __restrict__ s1,
                                const float* __restrict__ t2, const float* __restrict__ s2) {
    int i = blockIdx.x * blockDim.x + threadIdx.x;
    if (i >= NTOT) return;
    float t, s;
    if (i < N0)            { t = t0[i];          s = s0[i]; }
    else if (i < N0 + N1)  { t = t1[i - N0];     s = s1[i - N0]; }
    else                   { t = t2[i - R_OFF2]; s = s2[i - R_OFF2]; }
    float sp = __logf(1.0f + __expf(s));       // sraw in [-2,0] -> safe
    float rr = 1.0f / (0.001f + sp + 1e-8f);
    g_r[i] = rr;
    g_c[i] = -t * rr;
}

// ---- main wavelet contraction (packed f32x2 over o-pairs) ----
// finsel: 0 -> fin (layer-0 x), 1 -> g_f1, 2 -> g_f2
__global__ __launch_bounds__(BDIM) void wav_kernel(const float* __restrict__ fin,
                                                   const float* __restrict__ w,
                                                   int I, int chunkI, int roff, int finsel) {
    __shared__ float xs[CH][BBLK];
    __shared__ float rs[CH][OB];
    __shared__ float cs[CH][OB];
    __shared__ float ws[CH][OB];

    const float* f = (finsel == 1) ? g_f1 : (finsel == 2) ? g_f2 : fin;

    const int tid = threadIdx.x;
    const int og = tid & 15;      // 16 o-groups of 4
    const int bg = tid >> 4;      // 8  b-groups of 4
    const int o0 = blockIdx.x * OB;
    const int b0 = blockIdx.y * BBLK;
    const int i0base = blockIdx.z * chunkI;

    const ull KP   = pack2(0.72134752044448170368f, 0.72134752044448170368f); // +0.5*log2(e)
    const ull SGN  = 0x8000000080000000ULL;

    ull acc[4][2];
#pragma unroll
    for (int a = 0; a < 4; a++) { acc[a][0] = 0ULL; acc[a][1] = 0ULL; }

    // staging-load index maps
    const int xb = tid >> 2;            // 0..31 (b row)
    const int xj = (tid & 3) * 8;       // i offset
    const int ol = tid >> 1;            // 0..63 (o row)
    const int oj = (tid & 1) * 16;      // i offset

    const float* xrow = f + (size_t)(b0 + xb) * I + xj;
    const float* rrow = g_r + roff + (size_t)(o0 + ol) * I + oj;
    const float* crow = g_c + roff + (size_t)(o0 + ol) * I + oj;
    const float* wrow = w          + (size_t)(o0 + ol) * I + oj;

    for (int ic = 0; ic < chunkI; ic += CH) {
        const int i0 = i0base + ic;

        {
            float4 v0 = *(const float4*)(xrow + i0);
            float4 v1 = *(const float4*)(xrow + i0 + 4);
            xs[xj + 0][xb] = v0.x; xs[xj + 1][xb] = v0.y;
            xs[xj + 2][xb] = v0.z; xs[xj + 3][xb] = v0.w;
            xs[xj + 4][xb] = v1.x; xs[xj + 5][xb] = v1.y;
            xs[xj + 6][xb] = v1.z; xs[xj + 7][xb] = v1.w;
        }
#pragma unroll
        for (int q = 0; q < 4; q++) {
            float4 rv = *(const float4*)(rrow + i0 + q * 4);
            rs[oj + q * 4 + 0][ol] = rv.x; rs[oj + q * 4 + 1][ol] = rv.y;
            rs[oj + q * 4 + 2][ol] = rv.z; rs[oj + q * 4 + 3][ol] = rv.w;
            float4 cv = *(const float4*)(crow + i0 + q * 4);
            cs[oj + q * 4 + 0][ol] = cv.x; cs[oj + q * 4 + 1][ol] = cv.y;
            cs[oj + q * 4 + 2][ol] = cv.z; cs[oj + q * 4 + 3][ol] = cv.w;
            float4 wv = *(const float4*)(wrow + i0 + q * 4);
            ws[oj + q * 4 + 0][ol] = wv.x; ws[oj + q * 4 + 1][ol] = wv.y;
            ws[oj + q * 4 + 2][ol] = wv.z; ws[oj + q * 4 + 3][ol] = wv.w;
        }
        __syncthreads();

#pragma unroll 2
        for (int i = 0; i < CH; i++) {
            float4 x4 = *(const float4*)&xs[i][bg * 4];
            ull xp[4];
            xp[0] = pack2(x4.x, x4.x); xp[1] = pack2(x4.y, x4.y);
            xp[2] = pack2(x4.z, x4.z); xp[3] = pack2(x4.w, x4.w);
            // params packed over adjacent o (contiguous in smem row)
            const ull* rp = (const ull*)&rs[i][og * 4];
            const ull* cp = (const ull*)&cs[i][og * 4];
            const ull* wp = (const ull*)&ws[i][og * 4];
#pragma unroll
            for (int op = 0; op < 2; op++) {
                ull rr = rp[op], cc = cp[op], ww = wp[op];
#pragma unroll
                for (int bb = 0; bb < 4; bb++) {
                    ull s, u, g, p, e2;
                    fma2(s, xp[bb], rr, cc);        // s = x*r + c
                    mul2(u, s, s);                  // u = s^2
                    ull un = u ^ SGN;               // un = -s^2 (ALU pipe)
                    mul2(g, un, KP);                // g = -0.5*log2e * u
                    float g0, g1;
                    unpack2(g0, g1, g);
                    float e0 = ex2f(g0), e1 = ex2f(g1);
                    e2 = pack2(e0, e1);
                    fma2(p, un, ww, ww);            // p = w*(1-u)
                    fma2(acc[bb][op], p, e2, acc[bb][op]);
                }
            }
        }
        __syncthreads();
    }

    float* dst = g_part + (size_t)blockIdx.z * (BATCH * HID)
               + (size_t)(b0 + bg * 4) * HID + o0 + og * 4;
#pragma unroll
    for (int bb = 0; bb < 4; bb++) {
        float4 st;
        unpack2(st.x, st.y, acc[bb][0]);
        unpack2(st.z, st.w, acc[bb][1]);
        *(float4*)(dst + (size_t)bb * HID) = st;
    }
}

// ---- split-K reduce + SiLU + LayerNorm (+ optional classifier) ----
__global__ __launch_bounds__(128) void reduce_kernel(const float* __restrict__ gamma,
                                                     const float* __restrict__ beta,
                                                     const float* __restrict__ cw,
                                                     const float* __restrict__ cb,
                                                     float* __restrict__ out,
                                                     int outsel) {
    const int b = blockIdx.x;
    const int tid = threadIdx.x;
    const int wid = tid >> 5, lane = tid & 31;
    __shared__ float s1[4], s2[4];

    float v[4];
    float lsum = 0.0f, lsq = 0.0f;
#pragma unroll
    for (int q = 0; q < 4; q++) {
        int o = tid + q * 128;
        float z = 0.0f;
#pragma unroll
        for (int k = 0; k < KSPLIT; k++)
            z += g_part[(size_t)k * (BATCH * HID) + (size_t)b * HID + o];
        float sig = 1.0f / (1.0f + __expf(-z));
        float a = z * sig;
        v[q] = a;
        lsum += a;
        lsq = fmaf(a, a, lsq);
    }
#pragma unroll
    for (int off = 16; off; off >>= 1) {
        lsum += __shfl_xor_sync(0xffffffffu, lsum, off);
        lsq  += __shfl_xor_sync(0xffffffffu, lsq, off);
    }
    if (lane == 0) { s1[wid] = lsum; s2[wid] = lsq; }
    __syncthreads();
    float tsum = s1[0] + s1[1] + s1[2] + s1[3];
    float tsq  = s2[0] + s2[1] + s2[2] + s2[3];
    float mean = tsum * (1.0f / HID);
    float var  = tsq * (1.0f / HID) - mean * mean;
    float rstd = rsqrtf(var + 1e-5f);

    float d0 = 0.0f, d1 = 0.0f;
    float* fout = (outsel == 1) ? g_f1 : g_f2;
#pragma unroll
    for (int q = 0; q < 4; q++) {
        int o = tid + q * 128;
        float y = (v[q] - mean) * rstd * gamma[o] + beta[o];
        if (outsel == 0) {
            d0 = fmaf(y, cw[o], d0);
            d1 = fmaf(y, cw[HID + o], d1);
        } else {
            fout[(size_t)b * HID + o] = y;
        }
    }
    if (outsel == 0) {
#pragma unroll
        for (int off = 16; off; off >>= 1) {
            d0 += __shfl_xor_sync(0xffffffffu, d0, off);
            d1 += __shfl_xor_sync(0xffffffffu, d1, off);
        }
        __syncthreads();
        if (lane == 0) { s1[wid] = d0; s2[wid] = d1; }
        __syncthreads();
        if (tid == 0) {
            out[b * 2 + 0] = s1[0] + s1[1] + s1[2] + s1[3] + cb[0];
            out[b * 2 + 1] = s2[0] + s2[1] + s2[2] + s2[3] + cb[1];
        }
    }
}

extern "C" void kernel_launch(void* const* d_in, const int* in_sizes, int n_in,
                              void* d_out, int out_size) {
    const float* x  = (const float*)d_in[0];
    const float* t0 = (const float*)d_in[1];
    const float* s0 = (const float*)d_in[2];
    const float* w0 = (const float*)d_in[3];
    const float* g0 = (const float*)d_in[4];
    const float* b0 = (const float*)d_in[5];
    const float* t1 = (const float*)d_in[6];
    const float* s1 = (const float*)d_in[7];
    const float* w1 = (const float*)d_in[8];
    const float* g1 = (const float*)d_in[9];
    const float* b1 = (const float*)d_in[10];
    const float* t2 = (const float*)d_in[11];
    const float* s2 = (const float*)d_in[12];
    const float* w2 = (const float*)d_in[13];
    const float* g2 = (const float*)d_in[14];
    const float* b2 = (const float*)d_in[15];
    const float* cw = (const float*)d_in[16];
    const float* cb = (const float*)d_in[17];
    float* out = (float*)d_out;

    dim3 gmain(HID / OB, BATCH / BBLK, KSPLIT); // (8, 8, 16) = 1024 blocks

    // all param transforms up front, one launch
    prep_all_kernel<<<(NTOT + 255) / 256, 256>>>(t0, s0, t1, s1, t2, s2);

    // layer 0
    wav_kernel<<<gmain, BDIM>>>(x, w0, DIN, DIN / KSPLIT, 0, 0);
    reduce_kernel<<<BATCH, 128>>>(g0, b0, cw, cb, out, 1);

    // layer 1
    wav_kernel<<<gmain, BDIM>>>(nullptr, w1, HID, HID / KSPLIT, R_OFF1, 1);
    reduce_kernel<<<BATCH, 128>>>(g1, b1, cw, cb, out, 2);

    // layer 2 (+ classifier)
    wav_kernel<<<gmain, BDIM>>>(nullptr, w2, HID, HID / KSPLIT, R_OFF2, 2);
    reduce_kernel<<<BATCH, 128>>>(g2, b2, cw, cb, out, 0);
}

// round 3
// speedup vs baseline: 1.0999x; 1.0999x over previous
#include <cuda_runtime.h>
#include <cstdint>

#define CH    16
#define OBLK  64
#define BBLK  64
#define KS    32
#define BATCH 256
#define HID   512
#define DIN   2048

#define N0   (HID * DIN)
#define N1   (HID * HID)
#define OFF1 (N0)
#define OFF2 (N0 + N1)
#define NTOT (N0 + 2 * N1)

typedef unsigned long long ull;

// ---- device scratch (no allocations allowed) ----
__device__ float g_rp[NTOT];            // transposed [i][o], r*sqrt(K)
__device__ float g_cp[NTOT];            // -t*r*sqrt(K)
__device__ float g_wk[NTOT];            // w/K
__device__ float g_wt[NTOT];            // w
__device__ float g_xt[DIN * BATCH];     // x transposed [i][b]
__device__ float g_f1t[HID * BATCH];    // layer outputs transposed [o][b]
__device__ float g_f2t[HID * BATCH];
__device__ float g_part[KS * BATCH * HID];

// ---- packed f32x2 helpers ----
__device__ __forceinline__ void fma2(ull& d, ull a, ull b, ull c) {
    asm("fma.rn.f32x2 %0, %1, %2, %3;" : "=l"(d) : "l"(a), "l"(b), "l"(c));
}
__device__ __forceinline__ void mul2(ull& d, ull a, ull b) {
    asm("mul.rn.f32x2 %0, %1, %2;" : "=l"(d) : "l"(a), "l"(b));
}
__device__ __forceinline__ ull pack2(float lo, float hi) {
    ull r; asm("mov.b64 %0, {%1, %2};" : "=l"(r) : "f"(lo), "f"(hi)); return r;
}
__device__ __forceinline__ void unpack2(float& lo, float& hi, ull v) {
    asm("mov.b64 {%0, %1}, %2;" : "=f"(lo), "=f"(hi) : "l"(v));
}
__device__ __forceinline__ float ex2f(float g) {
    float e; asm("ex2.approx.ftz.f32 %0, %1;" : "=f"(e) : "f"(g)); return e;
}
__device__ __forceinline__ uint32_t s2u(const void* p) {
    return (uint32_t)__cvta_generic_to_shared(p);
}
__device__ __forceinline__ void cpa16(void* dst, const float* src) {
    asm volatile("cp.async.cg.shared.global [%0], [%1], 16;"
                 :: "r"(s2u(dst)), "l"(src) : "memory");
}

// ---- prep: transform + transpose params into [i][o] layout ----
__global__ void prep_tr_kernel(const float* __restrict__ t, const float* __restrict__ s,
                               const float* __restrict__ w, int I, int off) {
    __shared__ float sm[4][32][33];
    const int i0 = blockIdx.x * 32, o0 = blockIdx.y * 32;
    const int tx = threadIdx.x, ty = threadIdx.y;
    const float K = 0.72134752044448170368f;      // 0.5*log2(e)
    const float SQK = sqrtf(K);
    const float IK = 1.0f / K;
#pragma unroll
    for (int k = 0; k < 4; k++) {
        int ol = ty + k * 8;
        size_t idx = (size_t)(o0 + ol) * I + i0 + tx;
        float tv = t[idx], sv = s[idx], wv = w[idx];
        float den = 0.001f + log1pf(__expf(sv)) + 1e-8f;
        float r = SQK / den;
        sm[0][ol][tx] = r;
        sm[1][ol][tx] = -tv * r;
        sm[2][ol][tx] = wv * IK;
        sm[3][ol][tx] = wv;
    }
    __syncthreads();
#pragma unroll
    for (int k = 0; k < 4; k++) {
        int il = ty + k * 8;
        size_t odx = (size_t)off + (size_t)(i0 + il) * HID + o0 + tx;
        g_rp[odx] = sm[0][tx][il];
        g_cp[odx] = sm[1][tx][il];
        g_wk[odx] = sm[2][tx][il];
        g_wt[odx] = sm[3][tx][il];
    }
}

// ---- transpose x [B][DIN] -> g_xt [DIN][B] ----
__global__ void xpose_kernel(const float* __restrict__ x) {
    __shared__ float sm[32][33];
    const int i0 = blockIdx.x * 32, b0 = blockIdx.y * 32;
    const int tx = threadIdx.x, ty = threadIdx.y;
#pragma unroll
    for (int k = 0; k < 4; k++)
        sm[ty + k * 8][tx] = x[(size_t)(b0 + ty + k * 8) * DIN + i0 + tx];
    __syncthreads();
#pragma unroll
    for (int k = 0; k < 4; k++)
        g_xt[(size_t)(i0 + ty + k * 8) * BATCH + b0 + tx] = sm[tx][ty + k * 8];
}

// ---- wav kernel ----
struct __align__(16) Buf {
    float2 xd[CH][BBLK];   // x duplicated per lane-pair, 8KB
    float  rp[CH][OBLK];   // 4KB each
    float  cp[CH][OBLK];
    float  wk[CH][OBLK];
    float  wt[CH][OBLK];
};

__device__ __forceinline__ void stage_params(Buf* b, int i0, int o0, int off) {
    int c0 = threadIdx.x * 2;
#pragma unroll
    for (int j = 0; j < 2; j++) {
        int c = c0 + j, r = c >> 4, cc = (c & 15) * 4;
        size_t src = (size_t)off + (size_t)(i0 + r) * HID + o0 + cc;
        cpa16(&b->rp[r][cc], g_rp + src);
        cpa16(&b->cp[r][cc], g_cp + src);
        cpa16(&b->wk[r][cc], g_wk + src);
        cpa16(&b->wt[r][cc], g_wt + src);
    }
    asm volatile("cp.async.commit_group;" ::: "memory");
}

__device__ __forceinline__ void ldg_x(float4& a, float4& b, const float* xt, int i0, int b0) {
    const float* p = xt + (size_t)(i0 + (threadIdx.x >> 3)) * BATCH + b0 + (threadIdx.x & 7) * 8;
    a = *(const float4*)p;
    b = *(const float4*)(p + 4);
}
__device__ __forceinline__ void sts_x(Buf* bf, float4 a, float4 b) {
    float4* d = (float4*)&bf->xd[threadIdx.x >> 3][(threadIdx.x & 7) * 8];
    d[0] = make_float4(a.x, a.x, a.y, a.y);
    d[1] = make_float4(a.z, a.z, a.w, a.w);
    d[2] = make_float4(b.x, b.x, b.y, b.y);
    d[3] = make_float4(b.z, b.z, b.w, b.w);
}

// xsel: 0 -> g_xt, 1 -> g_f1t, 2 -> g_f2t
__global__ __launch_bounds__(128) void wav_kernel(int I, int off, int xsel) {
    __shared__ Buf sb[2];
    const float* xt = (xsel == 0) ? g_xt : (xsel == 1) ? g_f1t : g_f2t;

    const int tid = threadIdx.x;
    const int og = tid & 15, bg = tid >> 4;
    const int o0 = blockIdx.x * OBLK;
    const int b0 = blockIdx.y * BBLK;
    const int chunkI = I / KS;
    const int ntile = chunkI / CH;
    const int ibase = blockIdx.z * chunkI;

    ull acc[2][8];
#pragma unroll
    for (int u = 0; u < 2; u++)
#pragma unroll
        for (int k = 0; k < 8; k++) acc[u][k] = 0ULL;

    stage_params(&sb[0], ibase, o0, off);
    float4 xa, xb;
    ldg_x(xa, xb, xt, ibase, b0);

    const ull SG = 0x8000000080000000ULL;

    for (int t = 0; t < ntile; t++) {
        Buf* cur = &sb[t & 1];
        sts_x(cur, xa, xb);
        bool has = (t + 1 < ntile);
        if (has) {
            stage_params(&sb[(t + 1) & 1], ibase + (t + 1) * CH, o0, off);
            ldg_x(xa, xb, xt, ibase + (t + 1) * CH, b0);
            asm volatile("cp.async.wait_group 1;" ::: "memory");
        } else {
            asm volatile("cp.async.wait_group 0;" ::: "memory");
        }
        __syncthreads();

#pragma unroll 2
        for (int i = 0; i < CH; i++) {
            ull xv[8];
            const ull* xr = (const ull*)&cur->xd[i][bg * 8];
#pragma unroll
            for (int k = 0; k < 8; k++) xv[k] = xr[k];
            const ull* rp2 = (const ull*)&cur->rp[i][og * 4];
            const ull* cp2 = (const ull*)&cur->cp[i][og * 4];
            const ull* wk2 = (const ull*)&cur->wk[i][og * 4];
            const ull* wt2 = (const ull*)&cur->wt[i][og * 4];
#pragma unroll
            for (int u = 0; u < 2; u++) {
                ull rr = rp2[u], cc = cp2[u], kk = wk2[u], ww = wt2[u];
#pragma unroll
                for (int k = 0; k < 8; k++) {
                    ull s, nu, p;
                    fma2(s, xv[k], rr, cc);       // s' = sqrtK * (x-t)/sc
                    ull ns = s ^ SG;              // -s'
                    mul2(nu, s, ns);              // nu = -K*s^2
                    float ga, gb; unpack2(ga, gb, nu);
                    ull e = pack2(ex2f(ga), ex2f(gb)); // exp(-s^2/2)
                    fma2(p, nu, kk, ww);          // w*(1-s^2)
                    fma2(acc[u][k], p, e, acc[u][k]);
                }
            }
        }
        __syncthreads();
    }

    float* dst = g_part + ((size_t)blockIdx.z * BATCH + b0 + bg * 8) * HID + o0 + og * 4;
#pragma unroll
    for (int k = 0; k < 8; k++) {
        float4 v;
        unpack2(v.x, v.y, acc[0][k]);
        unpack2(v.z, v.w, acc[1][k]);
        *(float4*)(dst + (size_t)k * HID) = v;
    }
}

// ---- split-K reduce + SiLU + LayerNorm (+ classifier) ----
// outsel: 1 -> g_f1t, 2 -> g_f2t (transposed), 0 -> classifier into out
__global__ __launch_bounds__(128) void reduce_kernel(const float* __restrict__ gamma,
                                                     const float* __restrict__ beta,
                                                     const float* __restrict__ cw,
                                                     const float* __restrict__ cb,
                                                     float* __restrict__ out,
                                                     int outsel) {
    const int b = blockIdx.x;
    const int tid = threadIdx.x;
    const int wid = tid >> 5, lane = tid & 31;
    __shared__ float r1[4], r2[4];

    const float4* src = (const float4*)(g_part + (size_t)b * HID + tid * 4);
    float4 z = make_float4(0.f, 0.f, 0.f, 0.f);
#pragma unroll
    for (int k = 0; k < KS; k++) {
        float4 v = src[(size_t)k * (BATCH * HID / 4)];
        z.x += v.x; z.y += v.y; z.z += v.z; z.w += v.w;
    }
    float a[4];
    float lsum = 0.f, lsq = 0.f;
#pragma unroll
    for (int j = 0; j < 4; j++) {
        float zz = ((float*)&z)[j];
        float sig = 1.0f / (1.0f + __expf(-zz));
        float av = zz * sig;
        a[j] = av;
        lsum += av;
        lsq = fmaf(av, av, lsq);
    }
#pragma unroll
    for (int off = 16; off; off >>= 1) {
        lsum += __shfl_xor_sync(0xffffffffu, lsum, off);
        lsq  += __shfl_xor_sync(0xffffffffu, lsq, off);
    }
    if (lane == 0) { r1[wid] = lsum; r2[wid] = lsq; }
    __syncthreads();
    float tsum = r1[0] + r1[1] + r1[2] + r1[3];
    float tsq  = r2[0] + r2[1] + r2[2] + r2[3];
    float mean = tsum * (1.0f / HID);
    float var  = tsq * (1.0f / HID) - mean * mean;
    float rstd = rsqrtf(var + 1e-5f);

    float4 gm = ((const float4*)gamma)[tid];
    float4 bt = ((const float4*)beta)[tid];
    float d0 = 0.f, d1 = 0.f;
    float* ft = (outsel == 1) ? g_f1t : g_f2t;
#pragma unroll
    for (int j = 0; j < 4; j++) {
        int o = tid * 4 + j;
        float y = (a[j] - mean) * rstd * ((float*)&gm)[j] + ((float*)&bt)[j];
        if (outsel == 0) {
            d0 = fmaf(y, cw[o], d0);
            d1 = fmaf(y, cw[HID + o], d1);
        } else {
            ft[(size_t)o * BATCH + b] = y;
        }
    }
    if (outsel == 0) {
#pragma unroll
        for (int off = 16; off; off >>= 1) {
            d0 += __shfl_xor_sync(0xffffffffu, d0, off);
            d1 += __shfl_xor_sync(0xffffffffu, d1, off);
        }
        __syncthreads();
        if (lane == 0) { r1[wid] = d0; r2[wid] = d1; }
        __syncthreads();
        if (tid == 0) {
            out[b * 2 + 0] = r1[0] + r1[1] + r1[2] + r1[3] + cb[0];
            out[b * 2 + 1] = r2[0] + r2[1] + r2[2] + r2[3] + cb[1];
        }
    }
}

extern "C" void kernel_launch(void* const* d_in, const int* in_sizes, int n_in,
                              void* d_out, int out_size) {
    const float* x  = (const float*)d_in[0];
    const float* t0 = (const float*)d_in[1];
    const float* s0 = (const float*)d_in[2];
    const float* w0 = (const float*)d_in[3];
    const float* g0 = (const float*)d_in[4];
    const float* b0 = (const float*)d_in[5];
    const float* t1 = (const float*)d_in[6];
    const float* s1 = (const float*)d_in[7];
    const float* w1 = (const float*)d_in[8];
    const float* g1 = (const float*)d_in[9];
    const float* b1 = (const float*)d_in[10];
    const float* t2 = (const float*)d_in[11];
    const float* s2 = (const float*)d_in[12];
    const float* w2 = (const float*)d_in[13];
    const float* g2 = (const float*)d_in[14];
    const float* b2 = (const float*)d_in[15];
    const float* cw = (const float*)d_in[16];
    const float* cb = (const float*)d_in[17];
    float* out = (float*)d_out;

    dim3 tb(32, 8);
    prep_tr_kernel<<<dim3(DIN / 32, HID / 32), tb>>>(t0, s0, w0, DIN, 0);
    prep_tr_kernel<<<dim3(HID / 32, HID / 32), tb>>>(t1, s1, w1, HID, OFF1);
    prep_tr_kernel<<<dim3(HID / 32, HID / 32), tb>>>(t2, s2, w2, HID, OFF2);
    xpose_kernel<<<dim3(DIN / 32, BATCH / 32), tb>>>(x);

    dim3 gw(HID / OBLK, BATCH / BBLK, KS);  // (8, 4, 32) = 1024 blocks

    wav_kernel<<<gw, 128>>>(DIN, 0, 0);
    reduce_kernel<<<BATCH, 128>>>(g0, b0, cw, cb, out, 1);

    wav_kernel<<<gw, 128>>>(HID, OFF1, 1);
    reduce_kernel<<<BATCH, 128>>>(g1, b1, cw, cb, out, 2);

    wav_kernel<<<gw, 128>>>(HID, OFF2, 2);
    reduce_kernel<<<BATCH, 128>>>(g2, b2, cw, cb, out, 0);
}